// round 1
// baseline (speedup 1.0000x reference)
#include <cuda_runtime.h>
#include <math.h>

#define B_   2
#define SQ_  2048
#define SKV_ 2048
#define D_   1024
#define H_   16
#define HD_  64

// ---------------- scratch (no cudaMalloc allowed) ----------------
__device__ float g_Q[B_*SQ_*D_];
__device__ float g_K[B_*SKV_*D_];
__device__ float g_V[B_*SKV_*D_];
__device__ float g_ctx[B_*SQ_*D_];
__device__ float g_cos[SQ_*32];
__device__ float g_sin[SQ_*32];

// ---------------- GEMM: C[M,N] = A[M,K] @ W[N,K]^T + bias[N] ----------------
// BM=BN=128, BK=16, 256 threads, 8x8 per thread.
__global__ __launch_bounds__(256) void gemm_bias_kernel(
    const float* __restrict__ A, const float* __restrict__ W,
    const float* __restrict__ bias, float* __restrict__ C,
    int M, int N, int K)
{
    __shared__ float As[16][132];
    __shared__ float Ws[16][132];

    const int t  = threadIdx.x;
    const int tx = t & 15;
    const int ty = t >> 4;
    const int rowBase = blockIdx.y * 128;
    const int colBase = blockIdx.x * 128;

    float acc[8][8];
#pragma unroll
    for (int i = 0; i < 8; ++i)
#pragma unroll
        for (int j = 0; j < 8; ++j) acc[i][j] = 0.f;

    for (int kb = 0; kb < K; kb += 16) {
#pragma unroll
        for (int i = 0; i < 2; ++i) {
            int lin = t + i * 256;        // 0..511 (512 float4 per tile)
            int r   = lin >> 2;           // 0..127
            int c4  = (lin & 3) << 2;     // 0,4,8,12
            float4 av = *(const float4*)&A[(size_t)(rowBase + r) * K + kb + c4];
            As[c4+0][r] = av.x; As[c4+1][r] = av.y; As[c4+2][r] = av.z; As[c4+3][r] = av.w;
            float4 wv = *(const float4*)&W[(size_t)(colBase + r) * K + kb + c4];
            Ws[c4+0][r] = wv.x; Ws[c4+1][r] = wv.y; Ws[c4+2][r] = wv.z; Ws[c4+3][r] = wv.w;
        }
        __syncthreads();

#pragma unroll
        for (int k = 0; k < 16; ++k) {
            float a[8], w[8];
            *(float4*)&a[0] = *(const float4*)&As[k][ty * 8];
            *(float4*)&a[4] = *(const float4*)&As[k][ty * 8 + 4];
            *(float4*)&w[0] = *(const float4*)&Ws[k][tx * 8];
            *(float4*)&w[4] = *(const float4*)&Ws[k][tx * 8 + 4];
#pragma unroll
            for (int i = 0; i < 8; ++i)
#pragma unroll
                for (int j = 0; j < 8; ++j)
                    acc[i][j] = fmaf(a[i], w[j], acc[i][j]);
        }
        __syncthreads();
    }

#pragma unroll
    for (int i = 0; i < 8; ++i) {
        int row = rowBase + ty * 8 + i;
#pragma unroll
        for (int j4 = 0; j4 < 8; j4 += 4) {
            int col = colBase + tx * 8 + j4;
            float4 o;
            o.x = acc[i][j4+0] + bias[col+0];
            o.y = acc[i][j4+1] + bias[col+1];
            o.z = acc[i][j4+2] + bias[col+2];
            o.w = acc[i][j4+3] + bias[col+3];
            *(float4*)&C[(size_t)row * N + col] = o;
        }
    }
}

// ---------------- RoPE table (accurate sin/cos via fp64 arg) ----------------
__global__ void rope_table_kernel()
{
    int idx = blockIdx.x * blockDim.x + threadIdx.x;
    if (idx >= SQ_ * 32) return;
    int s = idx >> 5;
    int i = idx & 31;
    // match reference: freq rounded to fp32, angle = fp32(s) * fp32(freq),
    // then accurate sin/cos of that fp32 angle.
    float freq = (float)exp(-(double)i * log(10000.0) / 32.0);
    float ang  = (float)s * freq;
    double d   = (double)ang;
    g_cos[idx] = (float)cos(d);
    g_sin[idx] = (float)sin(d);
}

// ---------------- RoPE apply (interleaved pairs, in place) ----------------
__global__ void rope_apply_kernel(float* __restrict__ x, int S)
{
    int idx = blockIdx.x * blockDim.x + threadIdx.x;
    int total = B_ * S * H_ * 32;
    if (idx >= total) return;
    int i = idx & 31;
    int h = (idx >> 5) & (H_ - 1);
    int s = (idx >> 9) % S;
    int b = idx / (S * 512);
    size_t off = ((size_t)((b * S + s) * H_ + h)) * HD_ + 2 * i;
    float2 v = *(float2*)&x[off];
    float c  = g_cos[s * 32 + i];
    float sn = g_sin[s * 32 + i];
    float2 o;
    o.x = v.x * c - v.y * sn;
    o.y = v.x * sn + v.y * c;
    *(float2*)&x[off] = o;
}

// ---------------- Flash attention (fp32, online softmax) ----------------
// grid: (SQ/64, B*H), 256 threads. Each block: 64 q-rows x full KV sweep.
// thread layout: r = tid>>2 (q row), qd = tid&3.
// phase1: thread computes scores for j = 4*jj+qd (conflict-free Ks reads)
// phase2: thread accumulates ctx cols c = qd*16..qd*16+15.
#define PAD 68
__global__ __launch_bounds__(256) void flash_kernel()
{
    extern __shared__ float sm[];
    float (*Qs)[PAD] = (float(*)[PAD])(sm);
    float (*Ks)[PAD] = (float(*)[PAD])(sm + 64 * PAD);
    float (*Vs)[PAD] = (float(*)[PAD])(sm + 2 * 64 * PAD);
    float (*Ps)[PAD] = (float(*)[PAD])(sm + 3 * 64 * PAD);

    const int tid = threadIdx.x;
    const int qt  = blockIdx.x;
    const int bh  = blockIdx.y;
    const int b   = bh >> 4;
    const int h   = bh & 15;

    // load Q tile, pre-scaled by 1/sqrt(HD)
#pragma unroll
    for (int i = 0; i < 16; ++i) {
        int lin = tid + i * 256;
        int r = lin >> 6, c = lin & 63;
        Qs[r][c] = 0.125f * g_Q[((size_t)((b * SQ_ + qt * 64 + r) * H_ + h)) * HD_ + c];
    }

    const int r  = tid >> 2;
    const int qd = tid & 3;

    float m = -1e30f, l = 0.f;
    float4 acc[4];
#pragma unroll
    for (int i = 0; i < 4; ++i) acc[i] = make_float4(0.f, 0.f, 0.f, 0.f);

    __syncthreads();

    for (int t0 = 0; t0 < SKV_; t0 += 64) {
#pragma unroll
        for (int i = 0; i < 16; ++i) {
            int lin = tid + i * 256;
            int rr = lin >> 6, c = lin & 63;
            size_t base = ((size_t)((b * SKV_ + t0 + rr) * H_ + h)) * HD_ + c;
            Ks[rr][c] = g_K[base];
            Vs[rr][c] = g_V[base];
        }
        __syncthreads();

        // phase 1: scores
        float sv[16];
#pragma unroll
        for (int jj = 0; jj < 16; ++jj) sv[jj] = 0.f;
#pragma unroll
        for (int k4 = 0; k4 < 16; ++k4) {
            float4 qv = *(const float4*)&Qs[r][k4 * 4];
#pragma unroll
            for (int jj = 0; jj < 16; ++jj) {
                float4 kv = *(const float4*)&Ks[4 * jj + qd][k4 * 4];
                sv[jj] = fmaf(qv.x, kv.x, fmaf(qv.y, kv.y,
                          fmaf(qv.z, kv.z, fmaf(qv.w, kv.w, sv[jj]))));
            }
        }

        // row max over quad
        float mt = sv[0];
#pragma unroll
        for (int jj = 1; jj < 16; ++jj) mt = fmaxf(mt, sv[jj]);
        mt = fmaxf(mt, __shfl_xor_sync(0xffffffffu, mt, 1));
        mt = fmaxf(mt, __shfl_xor_sync(0xffffffffu, mt, 2));

        float mn   = fmaxf(m, mt);
        float corr = __expf(m - mn);
        float ps = 0.f;
#pragma unroll
        for (int jj = 0; jj < 16; ++jj) {
            float p = __expf(sv[jj] - mn);
            Ps[r][4 * jj + qd] = p;
            ps += p;
        }
        ps += __shfl_xor_sync(0xffffffffu, ps, 1);
        ps += __shfl_xor_sync(0xffffffffu, ps, 2);
        l = l * corr + ps;
        m = mn;
#pragma unroll
        for (int i = 0; i < 4; ++i) {
            acc[i].x *= corr; acc[i].y *= corr; acc[i].z *= corr; acc[i].w *= corr;
        }
        __syncwarp();   // Ps writes/reads are warp-local (quad of row r is in one warp)

        // phase 2: acc += P @ V
#pragma unroll
        for (int j = 0; j < 64; ++j) {
            float p = Ps[r][j];
#pragma unroll
            for (int c4 = 0; c4 < 4; ++c4) {
                float4 vv = *(const float4*)&Vs[j][qd * 16 + c4 * 4];
                acc[c4].x = fmaf(p, vv.x, acc[c4].x);
                acc[c4].y = fmaf(p, vv.y, acc[c4].y);
                acc[c4].z = fmaf(p, vv.z, acc[c4].z);
                acc[c4].w = fmaf(p, vv.w, acc[c4].w);
            }
        }
        __syncthreads();
    }

    float inv = 1.f / l;
    size_t ob = ((size_t)((b * SQ_ + qt * 64 + r) * H_ + h)) * HD_ + qd * 16;
#pragma unroll
    for (int c4 = 0; c4 < 4; ++c4) {
        float4 o;
        o.x = acc[c4].x * inv; o.y = acc[c4].y * inv;
        o.z = acc[c4].z * inv; o.w = acc[c4].w * inv;
        *(float4*)&g_ctx[ob + c4 * 4] = o;
    }
}

// ---------------- launch ----------------
extern "C" void kernel_launch(void* const* d_in, const int* in_sizes, int n_in,
                              void* d_out, int out_size)
{
    (void)in_sizes; (void)n_in; (void)out_size;
    const float* x_q  = (const float*)d_in[0];
    const float* x_kv = (const float*)d_in[1];
    const float* wq   = (const float*)d_in[2];
    const float* bq   = (const float*)d_in[3];
    const float* wk   = (const float*)d_in[4];
    const float* bk   = (const float*)d_in[5];
    const float* wv   = (const float*)d_in[6];
    const float* bv   = (const float*)d_in[7];
    const float* wo   = (const float*)d_in[8];
    const float* bo   = (const float*)d_in[9];
    float* out = (float*)d_out;

    float *Qp, *Kp, *Vp, *Cp;
    cudaGetSymbolAddress((void**)&Qp, g_Q);
    cudaGetSymbolAddress((void**)&Kp, g_K);
    cudaGetSymbolAddress((void**)&Vp, g_V);
    cudaGetSymbolAddress((void**)&Cp, g_ctx);

    const int M = B_ * SQ_;     // 4096
    dim3 gemmGrid(D_ / 128, M / 128);   // (8, 32)

    gemm_bias_kernel<<<gemmGrid, 256>>>(x_q,  wq, bq, Qp, M, D_, D_);
    gemm_bias_kernel<<<gemmGrid, 256>>>(x_kv, wk, bk, Kp, M, D_, D_);
    gemm_bias_kernel<<<gemmGrid, 256>>>(x_kv, wv, bv, Vp, M, D_, D_);

    rope_table_kernel<<<(SQ_ * 32 + 255) / 256, 256>>>();
    rope_apply_kernel<<<(B_ * SQ_  * H_ * 32 + 255) / 256, 256>>>(Qp, SQ_);
    rope_apply_kernel<<<(B_ * SKV_ * H_ * 32 + 255) / 256, 256>>>(Kp, SKV_);

    int smem = 4 * 64 * PAD * (int)sizeof(float);   // 69632 bytes
    cudaFuncSetAttribute(flash_kernel, cudaFuncAttributeMaxDynamicSharedMemorySize, smem);
    flash_kernel<<<dim3(SQ_ / 64, B_ * H_), 256, smem>>>();

    gemm_bias_kernel<<<gemmGrid, 256>>>(Cp, wo, bo, out, M, D_, D_);
}

// round 3
// speedup vs baseline: 7.4877x; 7.4877x over previous
#include <cuda_runtime.h>
#include <cuda_fp16.h>
#include <math.h>
#include <stdint.h>

#define B_   2
#define SQ_  2048
#define D_   1024
#define H_   16

// ---------------- scratch (no cudaMalloc allowed) ----------------
__device__ __half g_xqh[B_*SQ_*D_], g_xql[B_*SQ_*D_];
__device__ __half g_xkh[B_*SQ_*D_], g_xkl[B_*SQ_*D_];
__device__ __half g_wqh[D_*D_], g_wql[D_*D_];
__device__ __half g_wkh[D_*D_], g_wkl[D_*D_];
__device__ __half g_wvh[D_*D_], g_wvl[D_*D_];
__device__ __half g_woh[D_*D_], g_wol[D_*D_];
__device__ __half g_Qh[B_*SQ_*D_], g_Kh[B_*SQ_*D_], g_Vh[B_*SQ_*D_];
__device__ __half g_ch[B_*SQ_*D_], g_cl[B_*SQ_*D_];
__device__ float g_cos[SQ_*32], g_sin[SQ_*32];

// ---------------- helpers ----------------
__device__ __forceinline__ uint32_t smem_u32(const void* p) {
    uint32_t a;
    asm("{ .reg .u64 t; cvta.to.shared.u64 t, %1; cvt.u32.u64 %0, t; }"
        : "=r"(a) : "l"(p));
    return a;
}
__device__ __forceinline__ void cp16(uint32_t s, const void* g) {
    asm volatile("cp.async.cg.shared.global [%0], [%1], 16;" :: "r"(s), "l"(g));
}
#define CP_COMMIT() asm volatile("cp.async.commit_group;")
#define CP_WAIT(n)  asm volatile("cp.async.wait_group %0;" :: "n"(n))

__device__ __forceinline__ void ldsm4(uint32_t addr, uint32_t* r) {
    asm volatile("ldmatrix.sync.aligned.m8n8.x4.shared.b16 {%0,%1,%2,%3}, [%4];"
        : "=r"(r[0]), "=r"(r[1]), "=r"(r[2]), "=r"(r[3]) : "r"(addr));
}
__device__ __forceinline__ void ldsm4t(uint32_t addr, uint32_t* r) {
    asm volatile("ldmatrix.sync.aligned.m8n8.x4.trans.shared.b16 {%0,%1,%2,%3}, [%4];"
        : "=r"(r[0]), "=r"(r[1]), "=r"(r[2]), "=r"(r[3]) : "r"(addr));
}
__device__ __forceinline__ void mma_f16(float* c, const uint32_t* a, const uint32_t* b) {
    asm volatile(
        "mma.sync.aligned.m16n8k16.row.col.f32.f16.f16.f32 "
        "{%0,%1,%2,%3}, {%4,%5,%6,%7}, {%8,%9}, {%0,%1,%2,%3};"
        : "+f"(c[0]), "+f"(c[1]), "+f"(c[2]), "+f"(c[3])
        : "r"(a[0]), "r"(a[1]), "r"(a[2]), "r"(a[3]), "r"(b[0]), "r"(b[1]));
}
__device__ __forceinline__ uint32_t packh2(float x, float y) {
    __half2 t = __floats2half2_rn(x, y);
    return *reinterpret_cast<uint32_t*>(&t);
}

// ---------------- convert fp32 -> fp16 hi/lo planes ----------------
__global__ void split_kernel(const float* __restrict__ src,
                             __half* __restrict__ hi, __half* __restrict__ lo, int n4)
{
    int i = blockIdx.x * blockDim.x + threadIdx.x;
    if (i >= n4) return;
    float4 v = ((const float4*)src)[i];
    __half h0 = __float2half(v.x), h1 = __float2half(v.y);
    __half h2 = __float2half(v.z), h3 = __float2half(v.w);
    __half l0 = __float2half(v.x - __half2float(h0));
    __half l1 = __float2half(v.y - __half2float(h1));
    __half l2 = __float2half(v.z - __half2float(h2));
    __half l3 = __float2half(v.w - __half2float(h3));
    ((__half2*)hi)[2*i]   = __halves2half2(h0, h1);
    ((__half2*)hi)[2*i+1] = __halves2half2(h2, h3);
    ((__half2*)lo)[2*i]   = __halves2half2(l0, l1);
    ((__half2*)lo)[2*i+1] = __halves2half2(l2, l3);
}

// ---------------- RoPE table (accurate sin/cos via fp64) ----------------
__global__ void rope_table_kernel()
{
    int idx = blockIdx.x * blockDim.x + threadIdx.x;
    if (idx >= SQ_ * 32) return;
    int s = idx >> 5;
    int i = idx & 31;
    float freq = (float)exp(-(double)i * log(10000.0) / 32.0);
    float ang  = (float)s * freq;
    double d   = (double)ang;
    g_cos[idx] = (float)cos(d);
    g_sin[idx] = (float)sin(d);
}

// =============== GEMM (mma.sync fp16 split): C = A @ W^T + bias ===============
// BM=BN=128, BK=64, 256 threads (8 warps, 4x2), warp tile 32x64.
// A,W given as fp16 hi/lo planes [rows][1024]. Output: fp32 (Cf) or fp16 (Ch,
// with optional RoPE + scale).
#define GPS 18432   // plane bytes: 128 rows * 144
__global__ __launch_bounds__(256, 1) void gemm_split_kernel(
    const __half* __restrict__ Ah, const __half* __restrict__ Al,
    const __half* __restrict__ Wh, const __half* __restrict__ Wl,
    const float* __restrict__ bias,
    float* __restrict__ Cf, __half* __restrict__ Ch,
    int rope, float scale)
{
    const int K = D_, N = D_;
    extern __shared__ char smem[];
    const uint32_t sb = smem_u32(smem);
    const int tid  = threadIdx.x;
    const int lane = tid & 31, wid = tid >> 5;
    const int wm = wid >> 1, wn = wid & 1;
    const int rowBase = blockIdx.y * 128, colBase = blockIdx.x * 128;

    float acc[2][8][4];
#pragma unroll
    for (int i = 0; i < 2; ++i)
#pragma unroll
        for (int j = 0; j < 8; ++j)
#pragma unroll
            for (int q = 0; q < 4; ++q) acc[i][j][q] = 0.f;

    const __half* gsrc[4] = {Ah, Al, Wh, Wl};

#define GEMM_PREFETCH(kc, bf)                                                  \
    {                                                                          \
        _Pragma("unroll")                                                      \
        for (int p = 0; p < 4; ++p) {                                          \
            const __half* g = gsrc[p];                                         \
            int rb = (p < 2) ? rowBase : colBase;                              \
            _Pragma("unroll")                                                  \
            for (int i = 0; i < 4; ++i) {                                      \
                int id = tid + i * 256;                                        \
                int r = id >> 3, c = id & 7;                                   \
                cp16(sb + ((bf)*4 + p) * GPS + r * 144 + c * 16,               \
                     g + (size_t)(rb + r) * K + (kc) + c * 8);                 \
            }                                                                  \
        }                                                                      \
    }

    GEMM_PREFETCH(0, 0);
    CP_COMMIT();

    int buf = 0;
    for (int kc = 0; kc < K; kc += 64) {
        if (kc + 64 < K) {
            GEMM_PREFETCH(kc + 64, buf ^ 1);
            CP_COMMIT();
            CP_WAIT(1);
        } else {
            CP_WAIT(0);
        }
        __syncthreads();

        uint32_t base = sb + buf * 4 * GPS;
        uint32_t aA = base + (wm * 32 + (lane & 15)) * 144 + (lane >> 4) * 16;
        uint32_t aW = base + 2 * GPS
                    + (wn * 64 + ((lane >> 4) * 8 + (lane & 7))) * 144
                    + ((lane >> 3) & 1) * 16;
#pragma unroll
        for (int kst = 0; kst < 4; ++kst) {
            uint32_t ah0[4], ah1[4], al0[4], al1[4];
            ldsm4(aA + kst * 32, ah0);
            ldsm4(aA + kst * 32 + 16 * 144, ah1);
            ldsm4(aA + GPS + kst * 32, al0);
            ldsm4(aA + GPS + kst * 32 + 16 * 144, al1);
            uint32_t bh[8][2], bl[8][2];
#pragma unroll
            for (int p2 = 0; p2 < 4; ++p2) {
                uint32_t r[4];
                ldsm4(aW + p2 * 16 * 144 + kst * 32, r);
                bh[2*p2][0] = r[0]; bh[2*p2][1] = r[1];
                bh[2*p2+1][0] = r[2]; bh[2*p2+1][1] = r[3];
                ldsm4(aW + GPS + p2 * 16 * 144 + kst * 32, r);
                bl[2*p2][0] = r[0]; bl[2*p2][1] = r[1];
                bl[2*p2+1][0] = r[2]; bl[2*p2+1][1] = r[3];
            }
#pragma unroll
            for (int j = 0; j < 8; ++j) {
                mma_f16(acc[0][j], ah0, bh[j]);
                mma_f16(acc[0][j], ah0, bl[j]);
                mma_f16(acc[0][j], al0, bh[j]);
                mma_f16(acc[1][j], ah1, bh[j]);
                mma_f16(acc[1][j], ah1, bl[j]);
                mma_f16(acc[1][j], al1, bh[j]);
            }
        }
        __syncthreads();
        buf ^= 1;
    }

    // ---- epilogue ----
#pragma unroll
    for (int i = 0; i < 2; ++i) {
        int r0 = rowBase + wm * 32 + i * 16 + (lane >> 2);
        int r1 = r0 + 8;
#pragma unroll
        for (int j = 0; j < 8; ++j) {
            int c0 = colBase + wn * 64 + j * 8 + (lane & 3) * 2;
            float v00 = acc[i][j][0] + bias[c0];
            float v01 = acc[i][j][1] + bias[c0 + 1];
            float v10 = acc[i][j][2] + bias[c0];
            float v11 = acc[i][j][3] + bias[c0 + 1];
            if (Cf) {
                Cf[(size_t)r0 * N + c0]     = v00;
                Cf[(size_t)r0 * N + c0 + 1] = v01;
                Cf[(size_t)r1 * N + c0]     = v10;
                Cf[(size_t)r1 * N + c0 + 1] = v11;
            } else {
                if (rope) {
                    int ii = (c0 & 63) >> 1;
                    int s0 = r0 & (SQ_ - 1), s1 = r1 & (SQ_ - 1);
                    float cs = g_cos[s0 * 32 + ii], sn = g_sin[s0 * 32 + ii];
                    float e = v00, o = v01;
                    v00 = e * cs - o * sn; v01 = e * sn + o * cs;
                    cs = g_cos[s1 * 32 + ii]; sn = g_sin[s1 * 32 + ii];
                    e = v10; o = v11;
                    v10 = e * cs - o * sn; v11 = e * sn + o * cs;
                }
                v00 *= scale; v01 *= scale; v10 *= scale; v11 *= scale;
                __half2 h0 = __floats2half2_rn(v00, v01);
                __half2 h1 = __floats2half2_rn(v10, v11);
                *(__half2*)&Ch[(size_t)r0 * N + c0] = h0;
                *(__half2*)&Ch[(size_t)r1 * N + c0] = h1;
            }
        }
    }
}

// =============== Flash attention (mma.sync fp16, online softmax) ===============
// grid (SQ/64, B*H), 128 threads (4 warps), warp = 16 q-rows.
#define FPS 9216    // 64 rows * 144B
__global__ __launch_bounds__(128, 2) void flash16_kernel()
{
    extern __shared__ char smem[];
    const uint32_t sb = smem_u32(smem);
    const int tid = threadIdx.x, lane = tid & 31, wid = tid >> 5;
    const int qt = blockIdx.x, bh = blockIdx.y;
    const int b = bh >> 4, h = bh & 15;

    const uint32_t sQ = sb;

    // Q tile load (group 0)
#pragma unroll
    for (int i = 0; i < 4; ++i) {
        int id = tid + i * 128;
        int r = id >> 3, c = id & 7;
        cp16(sQ + r * 144 + c * 16,
             g_Qh + (((size_t)(b * SQ_ + qt * 64 + r)) * H_ + h) * 64 + c * 8);
    }
    CP_COMMIT();

#define KV_PREFETCH(t0, bf)                                                    \
    {                                                                          \
        _Pragma("unroll")                                                      \
        for (int i = 0; i < 4; ++i) {                                          \
            int id = tid + i * 128;                                            \
            int r = id >> 3, c = id & 7;                                       \
            size_t go = (((size_t)(b * SQ_ + (t0) + r)) * H_ + h) * 64 + c * 8;\
            cp16(sb + FPS + ((bf)*2 + 0) * FPS + r * 144 + c * 16, g_Kh + go); \
            cp16(sb + FPS + ((bf)*2 + 1) * FPS + r * 144 + c * 16, g_Vh + go); \
        }                                                                      \
    }

    KV_PREFETCH(0, 0);
    CP_COMMIT();

    float oacc[8][4];
#pragma unroll
    for (int j = 0; j < 8; ++j)
#pragma unroll
        for (int q = 0; q < 4; ++q) oacc[j][q] = 0.f;
    float m0 = -1e30f, m1 = -1e30f, l0 = 0.f, l1 = 0.f;
    uint32_t qf[4][4];

    int buf = 0;
    for (int t0 = 0; t0 < SQ_; t0 += 64) {
        if (t0 + 64 < SQ_) {
            KV_PREFETCH(t0 + 64, buf ^ 1);
            CP_COMMIT();
            CP_WAIT(1);
        } else {
            CP_WAIT(0);
        }
        __syncthreads();

        if (t0 == 0) {
            uint32_t aQ = sQ + (wid * 16 + (lane & 15)) * 144 + (lane >> 4) * 16;
#pragma unroll
            for (int kst = 0; kst < 4; ++kst) ldsm4(aQ + kst * 32, qf[kst]);
        }

        uint32_t sK = sb + FPS + (buf * 2) * FPS;
        uint32_t sV = sK + FPS;

        // ---- S = Q @ K^T ----
        float s[8][4];
#pragma unroll
        for (int j = 0; j < 8; ++j)
#pragma unroll
            for (int q = 0; q < 4; ++q) s[j][q] = 0.f;
        uint32_t aK = sK + ((lane >> 4) * 8 + (lane & 7)) * 144 + ((lane >> 3) & 1) * 16;
#pragma unroll
        for (int kst = 0; kst < 4; ++kst) {
#pragma unroll
            for (int p2 = 0; p2 < 4; ++p2) {
                uint32_t r[4];
                ldsm4(aK + p2 * 16 * 144 + kst * 32, r);
                mma_f16(s[2*p2],     qf[kst], &r[0]);
                mma_f16(s[2*p2 + 1], qf[kst], &r[2]);
            }
        }

        // ---- online softmax ----
        float mt0 = -1e30f, mt1 = -1e30f;
#pragma unroll
        for (int j = 0; j < 8; ++j) {
            mt0 = fmaxf(mt0, fmaxf(s[j][0], s[j][1]));
            mt1 = fmaxf(mt1, fmaxf(s[j][2], s[j][3]));
        }
        mt0 = fmaxf(mt0, __shfl_xor_sync(0xffffffffu, mt0, 1));
        mt0 = fmaxf(mt0, __shfl_xor_sync(0xffffffffu, mt0, 2));
        mt1 = fmaxf(mt1, __shfl_xor_sync(0xffffffffu, mt1, 1));
        mt1 = fmaxf(mt1, __shfl_xor_sync(0xffffffffu, mt1, 2));
        float mn0 = fmaxf(m0, mt0), mn1 = fmaxf(m1, mt1);
        float cr0 = __expf(m0 - mn0), cr1 = __expf(m1 - mn1);
        m0 = mn0; m1 = mn1;
        float ps0 = 0.f, ps1 = 0.f;
#pragma unroll
        for (int j = 0; j < 8; ++j) {
            s[j][0] = __expf(s[j][0] - mn0);
            s[j][1] = __expf(s[j][1] - mn0);
            s[j][2] = __expf(s[j][2] - mn1);
            s[j][3] = __expf(s[j][3] - mn1);
            ps0 += s[j][0] + s[j][1];
            ps1 += s[j][2] + s[j][3];
        }
        ps0 += __shfl_xor_sync(0xffffffffu, ps0, 1);
        ps0 += __shfl_xor_sync(0xffffffffu, ps0, 2);
        ps1 += __shfl_xor_sync(0xffffffffu, ps1, 1);
        ps1 += __shfl_xor_sync(0xffffffffu, ps1, 2);
        l0 = l0 * cr0 + ps0;
        l1 = l1 * cr1 + ps1;
#pragma unroll
        for (int j = 0; j < 8; ++j) {
            oacc[j][0] *= cr0; oacc[j][1] *= cr0;
            oacc[j][2] *= cr1; oacc[j][3] *= cr1;
        }

        // ---- P fragments (c-frag -> a-frag identity) ----
        uint32_t pf[4][4];
#pragma unroll
        for (int kt = 0; kt < 4; ++kt) {
            pf[kt][0] = packh2(s[2*kt][0],   s[2*kt][1]);
            pf[kt][1] = packh2(s[2*kt][2],   s[2*kt][3]);
            pf[kt][2] = packh2(s[2*kt+1][0], s[2*kt+1][1]);
            pf[kt][3] = packh2(s[2*kt+1][2], s[2*kt+1][3]);
        }

        // ---- O += P @ V ----
#pragma unroll
        for (int kt = 0; kt < 4; ++kt) {
            uint32_t aV = sV + (kt * 16 + (lane & 7) + ((lane >> 3) & 1) * 8) * 144
                        + (lane >> 4) * 16;
#pragma unroll
            for (int p2 = 0; p2 < 4; ++p2) {
                uint32_t r[4];
                ldsm4t(aV + p2 * 32, r);
                mma_f16(oacc[2*p2],     pf[kt], &r[0]);
                mma_f16(oacc[2*p2 + 1], pf[kt], &r[2]);
            }
        }
        __syncthreads();
        buf ^= 1;
    }

    // ---- normalize + write ctx hi/lo (fp16 split) ----
    float inv0 = 1.f / l0, inv1 = 1.f / l1;
    int r0 = qt * 64 + wid * 16 + (lane >> 2);
    size_t base0 = (((size_t)(b * SQ_ + r0)) * H_ + h) * 64;
    size_t base1 = base0 + (size_t)8 * H_ * 64;
#pragma unroll
    for (int j = 0; j < 8; ++j) {
        int c = j * 8 + (lane & 3) * 2;
        float v00 = oacc[j][0] * inv0, v01 = oacc[j][1] * inv0;
        float v10 = oacc[j][2] * inv1, v11 = oacc[j][3] * inv1;
        __half h00 = __float2half(v00), h01 = __float2half(v01);
        __half h10 = __float2half(v10), h11 = __float2half(v11);
        *(__half2*)&g_ch[base0 + c] = __halves2half2(h00, h01);
        *(__half2*)&g_ch[base1 + c] = __halves2half2(h10, h11);
        *(__half2*)&g_cl[base0 + c] = __halves2half2(
            __float2half(v00 - __half2float(h00)), __float2half(v01 - __half2float(h01)));
        *(__half2*)&g_cl[base1 + c] = __halves2half2(
            __float2half(v10 - __half2float(h10)), __float2half(v11 - __half2float(h11)));
    }
}

// ---------------- launch ----------------
extern "C" void kernel_launch(void* const* d_in, const int* in_sizes, int n_in,
                              void* d_out, int out_size)
{
    (void)in_sizes; (void)n_in; (void)out_size;
    const float* x_q  = (const float*)d_in[0];
    const float* x_kv = (const float*)d_in[1];
    const float* wq   = (const float*)d_in[2];
    const float* bq   = (const float*)d_in[3];
    const float* wk   = (const float*)d_in[4];
    const float* bk   = (const float*)d_in[5];
    const float* wv   = (const float*)d_in[6];
    const float* bv   = (const float*)d_in[7];
    const float* wo   = (const float*)d_in[8];
    const float* bo   = (const float*)d_in[9];
    float* out = (float*)d_out;

    __half *xqh, *xql, *xkh, *xkl, *wqh, *wql, *wkh, *wkl, *wvh, *wvl, *woh, *wol;
    __half *Qh, *Kh, *Vh, *ch, *cl;
    cudaGetSymbolAddress((void**)&xqh, g_xqh); cudaGetSymbolAddress((void**)&xql, g_xql);
    cudaGetSymbolAddress((void**)&xkh, g_xkh); cudaGetSymbolAddress((void**)&xkl, g_xkl);
    cudaGetSymbolAddress((void**)&wqh, g_wqh); cudaGetSymbolAddress((void**)&wql, g_wql);
    cudaGetSymbolAddress((void**)&wkh, g_wkh); cudaGetSymbolAddress((void**)&wkl, g_wkl);
    cudaGetSymbolAddress((void**)&wvh, g_wvh); cudaGetSymbolAddress((void**)&wvl, g_wvl);
    cudaGetSymbolAddress((void**)&woh, g_woh); cudaGetSymbolAddress((void**)&wol, g_wol);
    cudaGetSymbolAddress((void**)&Qh,  g_Qh);  cudaGetSymbolAddress((void**)&Kh,  g_Kh);
    cudaGetSymbolAddress((void**)&Vh,  g_Vh);
    cudaGetSymbolAddress((void**)&ch,  g_ch);  cudaGetSymbolAddress((void**)&cl,  g_cl);

    const int M  = B_ * SQ_;               // 4096
    const int NX = M * D_ / 4;             // float4 count for activations
    const int NW = D_ * D_ / 4;

    split_kernel<<<NX / 256, 256>>>(x_q,  xqh, xql, NX);
    split_kernel<<<NX / 256, 256>>>(x_kv, xkh, xkl, NX);
    split_kernel<<<NW / 256, 256>>>(wq, wqh, wql, NW);
    split_kernel<<<NW / 256, 256>>>(wk, wkh, wkl, NW);
    split_kernel<<<NW / 256, 256>>>(wv, wvh, wvl, NW);
    split_kernel<<<NW / 256, 256>>>(wo, woh, wol, NW);
    rope_table_kernel<<<(SQ_ * 32 + 255) / 256, 256>>>();

    dim3 gemmGrid(D_ / 128, M / 128);      // (8, 32)
    const int gemmSmem = 2 * 4 * GPS;      // 147456
    cudaFuncSetAttribute(gemm_split_kernel,
                         cudaFuncAttributeMaxDynamicSharedMemorySize, gemmSmem);

    gemm_split_kernel<<<gemmGrid, 256, gemmSmem>>>(xqh, xql, wqh, wql, bq,
                                                   nullptr, Qh, 1, 0.125f);
    gemm_split_kernel<<<gemmGrid, 256, gemmSmem>>>(xkh, xkl, wkh, wkl, bk,
                                                   nullptr, Kh, 1, 1.0f);
    gemm_split_kernel<<<gemmGrid, 256, gemmSmem>>>(xkh, xkl, wvh, wvl, bv,
                                                   nullptr, Vh, 0, 1.0f);

    const int flashSmem = 5 * FPS;         // 46080
    cudaFuncSetAttribute(flash16_kernel,
                         cudaFuncAttributeMaxDynamicSharedMemorySize, flashSmem);
    flash16_kernel<<<dim3(SQ_ / 64, B_ * H_), 128, flashSmem>>>();

    gemm_split_kernel<<<gemmGrid, 256, gemmSmem>>>(ch, cl, woh, wol, bo,
                                                   out, nullptr, 0, 1.0f);
}

// round 4
// speedup vs baseline: 9.1999x; 1.2287x over previous
#include <cuda_runtime.h>
#include <cuda_fp16.h>
#include <math.h>
#include <stdint.h>

#define B_   2
#define SQ_  2048
#define D_   1024
#define H_   16

// ---------------- scratch (no cudaMalloc allowed) ----------------
__device__ __half g_xqh[B_*SQ_*D_];
__device__ __half g_xkh[B_*SQ_*D_], g_xkl[B_*SQ_*D_];
__device__ __half g_wqh[D_*D_];
__device__ __half g_wkh[D_*D_];
__device__ __half g_wvh[D_*D_], g_wvl[D_*D_];
__device__ __half g_woh[D_*D_], g_wol[D_*D_];
__device__ __half g_Qh[B_*SQ_*D_], g_Kh[B_*SQ_*D_], g_Vh[B_*SQ_*D_];
__device__ __half g_ch[B_*SQ_*D_], g_cl[B_*SQ_*D_];
__device__ float g_cos[SQ_*32], g_sin[SQ_*32];

// ---------------- helpers ----------------
__device__ __forceinline__ uint32_t smem_u32(const void* p) {
    uint32_t a;
    asm("{ .reg .u64 t; cvta.to.shared.u64 t, %1; cvt.u32.u64 %0, t; }"
        : "=r"(a) : "l"(p));
    return a;
}
__device__ __forceinline__ void cp16(uint32_t s, const void* g) {
    asm volatile("cp.async.cg.shared.global [%0], [%1], 16;" :: "r"(s), "l"(g));
}
#define CP_COMMIT() asm volatile("cp.async.commit_group;")
#define CP_WAIT(n)  asm volatile("cp.async.wait_group %0;" :: "n"(n))

__device__ __forceinline__ void ldsm4(uint32_t addr, uint32_t* r) {
    asm volatile("ldmatrix.sync.aligned.m8n8.x4.shared.b16 {%0,%1,%2,%3}, [%4];"
        : "=r"(r[0]), "=r"(r[1]), "=r"(r[2]), "=r"(r[3]) : "r"(addr));
}
__device__ __forceinline__ void ldsm4t(uint32_t addr, uint32_t* r) {
    asm volatile("ldmatrix.sync.aligned.m8n8.x4.trans.shared.b16 {%0,%1,%2,%3}, [%4];"
        : "=r"(r[0]), "=r"(r[1]), "=r"(r[2]), "=r"(r[3]) : "r"(addr));
}
__device__ __forceinline__ void mma_f16(float* c, const uint32_t* a, const uint32_t* b) {
    asm volatile(
        "mma.sync.aligned.m16n8k16.row.col.f32.f16.f16.f32 "
        "{%0,%1,%2,%3}, {%4,%5,%6,%7}, {%8,%9}, {%0,%1,%2,%3};"
        : "+f"(c[0]), "+f"(c[1]), "+f"(c[2]), "+f"(c[3])
        : "r"(a[0]), "r"(a[1]), "r"(a[2]), "r"(a[3]), "r"(b[0]), "r"(b[1]));
}
__device__ __forceinline__ uint32_t packh2(float x, float y) {
    __half2 t = __floats2half2_rn(x, y);
    return *reinterpret_cast<uint32_t*>(&t);
}

// ---------------- converts ----------------
// three plain fp32->fp16 jobs in one launch
__global__ void conv_plain3_kernel(
    const float* __restrict__ s0, __half* __restrict__ d0, int n0,
    const float* __restrict__ s1, __half* __restrict__ d1, int n1,
    const float* __restrict__ s2, __half* __restrict__ d2, int n2)
{
    int i = blockIdx.x * blockDim.x + threadIdx.x;
    const float* s; __half* d;
    if (i < n0)            { s = s0; d = d0; }
    else if (i < n0 + n1)  { s = s1; d = d1; i -= n0; }
    else if (i < n0+n1+n2) { s = s2; d = d2; i -= n0 + n1; }
    else return;
    float4 v = ((const float4*)s)[i];
    ((__half2*)d)[2*i]   = __floats2half2_rn(v.x, v.y);
    ((__half2*)d)[2*i+1] = __floats2half2_rn(v.z, v.w);
}

// three split (hi/lo) jobs in one launch
__global__ void conv_split3_kernel(
    const float* __restrict__ s0, __half* __restrict__ h0, __half* __restrict__ l0p, int n0,
    const float* __restrict__ s1, __half* __restrict__ h1, __half* __restrict__ l1p, int n1,
    const float* __restrict__ s2, __half* __restrict__ h2, __half* __restrict__ l2p, int n2)
{
    int i = blockIdx.x * blockDim.x + threadIdx.x;
    const float* s; __half *hh, *ll;
    if (i < n0)            { s = s0; hh = h0; ll = l0p; }
    else if (i < n0 + n1)  { s = s1; hh = h1; ll = l1p; i -= n0; }
    else if (i < n0+n1+n2) { s = s2; hh = h2; ll = l2p; i -= n0 + n1; }
    else return;
    float4 v = ((const float4*)s)[i];
    __half a0 = __float2half(v.x), a1 = __float2half(v.y);
    __half a2 = __float2half(v.z), a3 = __float2half(v.w);
    ((__half2*)hh)[2*i]   = __halves2half2(a0, a1);
    ((__half2*)hh)[2*i+1] = __halves2half2(a2, a3);
    ((__half2*)ll)[2*i]   = __floats2half2_rn(v.x - __half2float(a0), v.y - __half2float(a1));
    ((__half2*)ll)[2*i+1] = __floats2half2_rn(v.z - __half2float(a2), v.w - __half2float(a3));
}

// ---------------- RoPE table (accurate sin/cos via fp64) ----------------
__global__ void rope_table_kernel()
{
    int idx = blockIdx.x * blockDim.x + threadIdx.x;
    if (idx >= SQ_ * 32) return;
    int s = idx >> 5;
    int i = idx & 31;
    float freq = (float)exp(-(double)i * log(10000.0) / 32.0);
    float ang  = (float)s * freq;
    double d   = (double)ang;
    g_cos[idx] = (float)cos(d);
    g_sin[idx] = (float)sin(d);
}

// =============== single-pass fp16 GEMM: Ch = (A @ W^T + bias) [rope/scale] ===============
// BM=BN=128, BK=64, 256 threads (8 warps 4x2), warp tile 32x64. Output fp16.
#define GPS 18432   // plane bytes: 128 rows * 144
__global__ __launch_bounds__(256, 1) void gemm_h_kernel(
    const __half* __restrict__ Ah, const __half* __restrict__ Wh,
    const float* __restrict__ bias, __half* __restrict__ Ch,
    int rope, float scale)
{
    const int K = D_, N = D_;
    extern __shared__ char smem[];
    const uint32_t sb = smem_u32(smem);
    const int tid  = threadIdx.x;
    const int lane = tid & 31, wid = tid >> 5;
    const int wm = wid >> 1, wn = wid & 1;
    const int rowBase = blockIdx.y * 128, colBase = blockIdx.x * 128;

    float acc[2][8][4];
#pragma unroll
    for (int i = 0; i < 2; ++i)
#pragma unroll
        for (int j = 0; j < 8; ++j)
#pragma unroll
            for (int q = 0; q < 4; ++q) acc[i][j][q] = 0.f;

#define GH_PREFETCH(kc, bf)                                                    \
    {                                                                          \
        _Pragma("unroll")                                                      \
        for (int i = 0; i < 4; ++i) {                                          \
            int id = tid + i * 256;                                            \
            int r = id >> 3, c = id & 7;                                       \
            cp16(sb + ((bf)*2 + 0) * GPS + r * 144 + c * 16,                   \
                 Ah + (size_t)(rowBase + r) * K + (kc) + c * 8);               \
            cp16(sb + ((bf)*2 + 1) * GPS + r * 144 + c * 16,                   \
                 Wh + (size_t)(colBase + r) * K + (kc) + c * 8);               \
        }                                                                      \
    }

    GH_PREFETCH(0, 0);
    CP_COMMIT();

    int buf = 0;
    for (int kc = 0; kc < K; kc += 64) {
        if (kc + 64 < K) {
            GH_PREFETCH(kc + 64, buf ^ 1);
            CP_COMMIT();
            CP_WAIT(1);
        } else {
            CP_WAIT(0);
        }
        __syncthreads();

        uint32_t base = sb + buf * 2 * GPS;
        uint32_t aA = base + (wm * 32 + (lane & 15)) * 144 + (lane >> 4) * 16;
        uint32_t aW = base + GPS
                    + (wn * 64 + ((lane >> 4) * 8 + (lane & 7))) * 144
                    + ((lane >> 3) & 1) * 16;
#pragma unroll
        for (int kst = 0; kst < 4; ++kst) {
            uint32_t a0[4], a1[4];
            ldsm4(aA + kst * 32, a0);
            ldsm4(aA + kst * 32 + 16 * 144, a1);
            uint32_t bh[8][2];
#pragma unroll
            for (int p2 = 0; p2 < 4; ++p2) {
                uint32_t r[4];
                ldsm4(aW + p2 * 16 * 144 + kst * 32, r);
                bh[2*p2][0] = r[0]; bh[2*p2][1] = r[1];
                bh[2*p2+1][0] = r[2]; bh[2*p2+1][1] = r[3];
            }
#pragma unroll
            for (int j = 0; j < 8; ++j) {
                mma_f16(acc[0][j], a0, bh[j]);
                mma_f16(acc[1][j], a1, bh[j]);
            }
        }
        __syncthreads();
        buf ^= 1;
    }

#pragma unroll
    for (int i = 0; i < 2; ++i) {
        int r0 = rowBase + wm * 32 + i * 16 + (lane >> 2);
        int r1 = r0 + 8;
#pragma unroll
        for (int j = 0; j < 8; ++j) {
            int c0 = colBase + wn * 64 + j * 8 + (lane & 3) * 2;
            float v00 = acc[i][j][0] + bias[c0];
            float v01 = acc[i][j][1] + bias[c0 + 1];
            float v10 = acc[i][j][2] + bias[c0];
            float v11 = acc[i][j][3] + bias[c0 + 1];
            if (rope) {
                int ii = (c0 & 63) >> 1;
                int s0 = r0 & (SQ_ - 1), s1 = r1 & (SQ_ - 1);
                float cs = g_cos[s0 * 32 + ii], sn = g_sin[s0 * 32 + ii];
                float e = v00, o = v01;
                v00 = e * cs - o * sn; v01 = e * sn + o * cs;
                cs = g_cos[s1 * 32 + ii]; sn = g_sin[s1 * 32 + ii];
                e = v10; o = v11;
                v10 = e * cs - o * sn; v11 = e * sn + o * cs;
            }
            v00 *= scale; v01 *= scale; v10 *= scale; v11 *= scale;
            *(__half2*)&Ch[(size_t)r0 * N + c0] = __floats2half2_rn(v00, v01);
            *(__half2*)&Ch[(size_t)r1 * N + c0] = __floats2half2_rn(v10, v11);
        }
    }
}

// =============== split GEMM (3-pass hi/lo): C = A @ W^T + bias ===============
__global__ __launch_bounds__(256, 1) void gemm_split_kernel(
    const __half* __restrict__ Ah, const __half* __restrict__ Al,
    const __half* __restrict__ Wh, const __half* __restrict__ Wl,
    const float* __restrict__ bias,
    float* __restrict__ Cf, __half* __restrict__ Ch)
{
    const int K = D_, N = D_;
    extern __shared__ char smem[];
    const uint32_t sb = smem_u32(smem);
    const int tid  = threadIdx.x;
    const int lane = tid & 31, wid = tid >> 5;
    const int wm = wid >> 1, wn = wid & 1;
    const int rowBase = blockIdx.y * 128, colBase = blockIdx.x * 128;

    float acc[2][8][4];
#pragma unroll
    for (int i = 0; i < 2; ++i)
#pragma unroll
        for (int j = 0; j < 8; ++j)
#pragma unroll
            for (int q = 0; q < 4; ++q) acc[i][j][q] = 0.f;

    const __half* gsrc[4] = {Ah, Al, Wh, Wl};

#define GEMM_PREFETCH(kc, bf)                                                  \
    {                                                                          \
        _Pragma("unroll")                                                      \
        for (int p = 0; p < 4; ++p) {                                          \
            const __half* g = gsrc[p];                                         \
            int rb = (p < 2) ? rowBase : colBase;                              \
            _Pragma("unroll")                                                  \
            for (int i = 0; i < 4; ++i) {                                      \
                int id = tid + i * 256;                                        \
                int r = id >> 3, c = id & 7;                                   \
                cp16(sb + ((bf)*4 + p) * GPS + r * 144 + c * 16,               \
                     g + (size_t)(rb + r) * K + (kc) + c * 8);                 \
            }                                                                  \
        }                                                                      \
    }

    GEMM_PREFETCH(0, 0);
    CP_COMMIT();

    int buf = 0;
    for (int kc = 0; kc < K; kc += 64) {
        if (kc + 64 < K) {
            GEMM_PREFETCH(kc + 64, buf ^ 1);
            CP_COMMIT();
            CP_WAIT(1);
        } else {
            CP_WAIT(0);
        }
        __syncthreads();

        uint32_t base = sb + buf * 4 * GPS;
        uint32_t aA = base + (wm * 32 + (lane & 15)) * 144 + (lane >> 4) * 16;
        uint32_t aW = base + 2 * GPS
                    + (wn * 64 + ((lane >> 4) * 8 + (lane & 7))) * 144
                    + ((lane >> 3) & 1) * 16;
#pragma unroll
        for (int kst = 0; kst < 4; ++kst) {
            uint32_t ah0[4], ah1[4], al0[4], al1[4];
            ldsm4(aA + kst * 32, ah0);
            ldsm4(aA + kst * 32 + 16 * 144, ah1);
            ldsm4(aA + GPS + kst * 32, al0);
            ldsm4(aA + GPS + kst * 32 + 16 * 144, al1);
            uint32_t bh[8][2], bl[8][2];
#pragma unroll
            for (int p2 = 0; p2 < 4; ++p2) {
                uint32_t r[4];
                ldsm4(aW + p2 * 16 * 144 + kst * 32, r);
                bh[2*p2][0] = r[0]; bh[2*p2][1] = r[1];
                bh[2*p2+1][0] = r[2]; bh[2*p2+1][1] = r[3];
                ldsm4(aW + GPS + p2 * 16 * 144 + kst * 32, r);
                bl[2*p2][0] = r[0]; bl[2*p2][1] = r[1];
                bl[2*p2+1][0] = r[2]; bl[2*p2+1][1] = r[3];
            }
#pragma unroll
            for (int j = 0; j < 8; ++j) {
                mma_f16(acc[0][j], ah0, bh[j]);
                mma_f16(acc[0][j], ah0, bl[j]);
                mma_f16(acc[0][j], al0, bh[j]);
                mma_f16(acc[1][j], ah1, bh[j]);
                mma_f16(acc[1][j], ah1, bl[j]);
                mma_f16(acc[1][j], al1, bh[j]);
            }
        }
        __syncthreads();
        buf ^= 1;
    }

#pragma unroll
    for (int i = 0; i < 2; ++i) {
        int r0 = rowBase + wm * 32 + i * 16 + (lane >> 2);
        int r1 = r0 + 8;
#pragma unroll
        for (int j = 0; j < 8; ++j) {
            int c0 = colBase + wn * 64 + j * 8 + (lane & 3) * 2;
            float v00 = acc[i][j][0] + bias[c0];
            float v01 = acc[i][j][1] + bias[c0 + 1];
            float v10 = acc[i][j][2] + bias[c0];
            float v11 = acc[i][j][3] + bias[c0 + 1];
            if (Cf) {
                Cf[(size_t)r0 * N + c0]     = v00;
                Cf[(size_t)r0 * N + c0 + 1] = v01;
                Cf[(size_t)r1 * N + c0]     = v10;
                Cf[(size_t)r1 * N + c0 + 1] = v11;
            } else {
                *(__half2*)&Ch[(size_t)r0 * N + c0] = __floats2half2_rn(v00, v01);
                *(__half2*)&Ch[(size_t)r1 * N + c0] = __floats2half2_rn(v10, v11);
            }
        }
    }
}

// =============== Flash attention (mma.sync fp16, online softmax) ===============
#define FPS 9216    // 64 rows * 144B
__global__ __launch_bounds__(128, 2) void flash16_kernel()
{
    extern __shared__ char smem[];
    const uint32_t sb = smem_u32(smem);
    const int tid = threadIdx.x, lane = tid & 31, wid = tid >> 5;
    const int qt = blockIdx.x, bh = blockIdx.y;
    const int b = bh >> 4, h = bh & 15;

    const uint32_t sQ = sb;

#pragma unroll
    for (int i = 0; i < 4; ++i) {
        int id = tid + i * 128;
        int r = id >> 3, c = id & 7;
        cp16(sQ + r * 144 + c * 16,
             g_Qh + (((size_t)(b * SQ_ + qt * 64 + r)) * H_ + h) * 64 + c * 8);
    }
    CP_COMMIT();

#define KV_PREFETCH(t0, bf)                                                    \
    {                                                                          \
        _Pragma("unroll")                                                      \
        for (int i = 0; i < 4; ++i) {                                          \
            int id = tid + i * 128;                                            \
            int r = id >> 3, c = id & 7;                                       \
            size_t go = (((size_t)(b * SQ_ + (t0) + r)) * H_ + h) * 64 + c * 8;\
            cp16(sb + FPS + ((bf)*2 + 0) * FPS + r * 144 + c * 16, g_Kh + go); \
            cp16(sb + FPS + ((bf)*2 + 1) * FPS + r * 144 + c * 16, g_Vh + go); \
        }                                                                      \
    }

    KV_PREFETCH(0, 0);
    CP_COMMIT();

    float oacc[8][4];
#pragma unroll
    for (int j = 0; j < 8; ++j)
#pragma unroll
        for (int q = 0; q < 4; ++q) oacc[j][q] = 0.f;
    float m0 = -1e30f, m1 = -1e30f, l0 = 0.f, l1 = 0.f;
    uint32_t qf[4][4];

    int buf = 0;
    for (int t0 = 0; t0 < SQ_; t0 += 64) {
        if (t0 + 64 < SQ_) {
            KV_PREFETCH(t0 + 64, buf ^ 1);
            CP_COMMIT();
            CP_WAIT(1);
        } else {
            CP_WAIT(0);
        }
        __syncthreads();

        if (t0 == 0) {
            uint32_t aQ = sQ + (wid * 16 + (lane & 15)) * 144 + (lane >> 4) * 16;
#pragma unroll
            for (int kst = 0; kst < 4; ++kst) ldsm4(aQ + kst * 32, qf[kst]);
        }

        uint32_t sK = sb + FPS + (buf * 2) * FPS;
        uint32_t sV = sK + FPS;

        float s[8][4];
#pragma unroll
        for (int j = 0; j < 8; ++j)
#pragma unroll
            for (int q = 0; q < 4; ++q) s[j][q] = 0.f;
        uint32_t aK = sK + ((lane >> 4) * 8 + (lane & 7)) * 144 + ((lane >> 3) & 1) * 16;
#pragma unroll
        for (int kst = 0; kst < 4; ++kst) {
#pragma unroll
            for (int p2 = 0; p2 < 4; ++p2) {
                uint32_t r[4];
                ldsm4(aK + p2 * 16 * 144 + kst * 32, r);
                mma_f16(s[2*p2],     qf[kst], &r[0]);
                mma_f16(s[2*p2 + 1], qf[kst], &r[2]);
            }
        }

        float mt0 = -1e30f, mt1 = -1e30f;
#pragma unroll
        for (int j = 0; j < 8; ++j) {
            mt0 = fmaxf(mt0, fmaxf(s[j][0], s[j][1]));
            mt1 = fmaxf(mt1, fmaxf(s[j][2], s[j][3]));
        }
        mt0 = fmaxf(mt0, __shfl_xor_sync(0xffffffffu, mt0, 1));
        mt0 = fmaxf(mt0, __shfl_xor_sync(0xffffffffu, mt0, 2));
        mt1 = fmaxf(mt1, __shfl_xor_sync(0xffffffffu, mt1, 1));
        mt1 = fmaxf(mt1, __shfl_xor_sync(0xffffffffu, mt1, 2));
        float mn0 = fmaxf(m0, mt0), mn1 = fmaxf(m1, mt1);
        float cr0 = __expf(m0 - mn0), cr1 = __expf(m1 - mn1);
        m0 = mn0; m1 = mn1;
        float ps0 = 0.f, ps1 = 0.f;
#pragma unroll
        for (int j = 0; j < 8; ++j) {
            s[j][0] = __expf(s[j][0] - mn0);
            s[j][1] = __expf(s[j][1] - mn0);
            s[j][2] = __expf(s[j][2] - mn1);
            s[j][3] = __expf(s[j][3] - mn1);
            ps0 += s[j][0] + s[j][1];
            ps1 += s[j][2] + s[j][3];
        }
        ps0 += __shfl_xor_sync(0xffffffffu, ps0, 1);
        ps0 += __shfl_xor_sync(0xffffffffu, ps0, 2);
        ps1 += __shfl_xor_sync(0xffffffffu, ps1, 1);
        ps1 += __shfl_xor_sync(0xffffffffu, ps1, 2);
        l0 = l0 * cr0 + ps0;
        l1 = l1 * cr1 + ps1;
#pragma unroll
        for (int j = 0; j < 8; ++j) {
            oacc[j][0] *= cr0; oacc[j][1] *= cr0;
            oacc[j][2] *= cr1; oacc[j][3] *= cr1;
        }

        uint32_t pf[4][4];
#pragma unroll
        for (int kt = 0; kt < 4; ++kt) {
            pf[kt][0] = packh2(s[2*kt][0],   s[2*kt][1]);
            pf[kt][1] = packh2(s[2*kt][2],   s[2*kt][3]);
            pf[kt][2] = packh2(s[2*kt+1][0], s[2*kt+1][1]);
            pf[kt][3] = packh2(s[2*kt+1][2], s[2*kt+1][3]);
        }

#pragma unroll
        for (int kt = 0; kt < 4; ++kt) {
            uint32_t aV = sV + (kt * 16 + (lane & 7) + ((lane >> 3) & 1) * 8) * 144
                        + (lane >> 4) * 16;
#pragma unroll
            for (int p2 = 0; p2 < 4; ++p2) {
                uint32_t r[4];
                ldsm4t(aV + p2 * 32, r);
                mma_f16(oacc[2*p2],     pf[kt], &r[0]);
                mma_f16(oacc[2*p2 + 1], pf[kt], &r[2]);
            }
        }
        __syncthreads();
        buf ^= 1;
    }

    float inv0 = 1.f / l0, inv1 = 1.f / l1;
    int r0 = qt * 64 + wid * 16 + (lane >> 2);
    size_t base0 = (((size_t)(b * SQ_ + r0)) * H_ + h) * 64;
    size_t base1 = base0 + (size_t)8 * H_ * 64;
#pragma unroll
    for (int j = 0; j < 8; ++j) {
        int c = j * 8 + (lane & 3) * 2;
        float v00 = oacc[j][0] * inv0, v01 = oacc[j][1] * inv0;
        float v10 = oacc[j][2] * inv1, v11 = oacc[j][3] * inv1;
        __half h00 = __float2half(v00), h01 = __float2half(v01);
        __half h10 = __float2half(v10), h11 = __float2half(v11);
        *(__half2*)&g_ch[base0 + c] = __halves2half2(h00, h01);
        *(__half2*)&g_ch[base1 + c] = __halves2half2(h10, h11);
        *(__half2*)&g_cl[base0 + c] = __halves2half2(
            __float2half(v00 - __half2float(h00)), __float2half(v01 - __half2float(h01)));
        *(__half2*)&g_cl[base1 + c] = __halves2half2(
            __float2half(v10 - __half2float(h10)), __float2half(v11 - __half2float(h11)));
    }
}

// ---------------- launch ----------------
extern "C" void kernel_launch(void* const* d_in, const int* in_sizes, int n_in,
                              void* d_out, int out_size)
{
    (void)in_sizes; (void)n_in; (void)out_size;
    const float* x_q  = (const float*)d_in[0];
    const float* x_kv = (const float*)d_in[1];
    const float* wq   = (const float*)d_in[2];
    const float* bq   = (const float*)d_in[3];
    const float* wk   = (const float*)d_in[4];
    const float* bk   = (const float*)d_in[5];
    const float* wv   = (const float*)d_in[6];
    const float* bv   = (const float*)d_in[7];
    const float* wo   = (const float*)d_in[8];
    const float* bo   = (const float*)d_in[9];
    float* out = (float*)d_out;

    __half *xqh, *xkh, *xkl, *wqh, *wkh, *wvh, *wvl, *woh, *wol;
    __half *Qh, *Kh, *Vh, *ch, *cl;
    cudaGetSymbolAddress((void**)&xqh, g_xqh);
    cudaGetSymbolAddress((void**)&xkh, g_xkh); cudaGetSymbolAddress((void**)&xkl, g_xkl);
    cudaGetSymbolAddress((void**)&wqh, g_wqh);
    cudaGetSymbolAddress((void**)&wkh, g_wkh);
    cudaGetSymbolAddress((void**)&wvh, g_wvh); cudaGetSymbolAddress((void**)&wvl, g_wvl);
    cudaGetSymbolAddress((void**)&woh, g_woh); cudaGetSymbolAddress((void**)&wol, g_wol);
    cudaGetSymbolAddress((void**)&Qh,  g_Qh);  cudaGetSymbolAddress((void**)&Kh,  g_Kh);
    cudaGetSymbolAddress((void**)&Vh,  g_Vh);
    cudaGetSymbolAddress((void**)&ch,  g_ch);  cudaGetSymbolAddress((void**)&cl,  g_cl);

    const int M  = B_ * SQ_;               // 4096
    const int NX = M * D_ / 4;             // 1,048,576 float4
    const int NW = D_ * D_ / 4;            // 262,144 float4

    // plain converts: x_q, wq, wk
    conv_plain3_kernel<<<(NX + 2*NW + 255) / 256, 256>>>(
        x_q, xqh, NX, wq, wqh, NW, wk, wkh, NW);
    // split converts: x_kv, wv, wo
    conv_split3_kernel<<<(NX + 2*NW + 255) / 256, 256>>>(
        x_kv, xkh, xkl, NX, wv, wvh, wvl, NW, wo, woh, wol, NW);
    rope_table_kernel<<<(SQ_ * 32 + 255) / 256, 256>>>();

    dim3 gemmGrid(D_ / 128, M / 128);      // (8, 32)
    const int ghSmem = 2 * 2 * GPS;        // 73728
    const int gsSmem = 2 * 4 * GPS;        // 147456
    cudaFuncSetAttribute(gemm_h_kernel,
                         cudaFuncAttributeMaxDynamicSharedMemorySize, ghSmem);
    cudaFuncSetAttribute(gemm_split_kernel,
                         cudaFuncAttributeMaxDynamicSharedMemorySize, gsSmem);

    gemm_h_kernel<<<gemmGrid, 256, ghSmem>>>(xqh, wqh, bq, Qh, 1, 0.125f);
    gemm_h_kernel<<<gemmGrid, 256, ghSmem>>>(xkh, wkh, bk, Kh, 1, 1.0f);
    gemm_split_kernel<<<gemmGrid, 256, gsSmem>>>(xkh, xkl, wvh, wvl, bv, nullptr, Vh);

    const int flashSmem = 5 * FPS;         // 46080
    cudaFuncSetAttribute(flash16_kernel,
                         cudaFuncAttributeMaxDynamicSharedMemorySize, flashSmem);
    flash16_kernel<<<dim3(SQ_ / 64, B_ * H_), 128, flashSmem>>>();

    gemm_split_kernel<<<gemmGrid, 256, gsSmem>>>(ch, cl, woh, wol, bo, out, nullptr);
}

// round 6
// speedup vs baseline: 11.1515x; 1.2121x over previous
#include <cuda_runtime.h>
#include <cuda_fp16.h>
#include <math.h>
#include <stdint.h>

#define B_   2
#define SQ_  2048
#define D_   1024
#define H_   16

// ---------------- scratch (no cudaMalloc allowed) ----------------
__device__ __half g_xqh[B_*SQ_*D_];
__device__ __half g_xkh[B_*SQ_*D_];
__device__ __half g_wqh[D_*D_];
__device__ __half g_wkh[D_*D_];
__device__ __half g_wvh[D_*D_];
__device__ __half g_woh[D_*D_], g_wol[D_*D_];
__device__ __half g_Qh[B_*SQ_*D_], g_Kh[B_*SQ_*D_], g_Vh[B_*SQ_*D_];
__device__ __half g_ch[B_*SQ_*D_], g_cl[B_*SQ_*D_];
__device__ float g_cos[SQ_*32], g_sin[SQ_*32];

// ---------------- helpers ----------------
__device__ __forceinline__ uint32_t smem_u32(const void* p) {
    uint32_t a;
    asm("{ .reg .u64 t; cvta.to.shared.u64 t, %1; cvt.u32.u64 %0, t; }"
        : "=r"(a) : "l"(p));
    return a;
}
__device__ __forceinline__ void cp16(uint32_t s, const void* g) {
    asm volatile("cp.async.cg.shared.global [%0], [%1], 16;" :: "r"(s), "l"(g));
}
#define CP_COMMIT() asm volatile("cp.async.commit_group;")
#define CP_WAIT(n)  asm volatile("cp.async.wait_group %0;" :: "n"(n))

__device__ __forceinline__ void ldsm4(uint32_t addr, uint32_t* r) {
    asm volatile("ldmatrix.sync.aligned.m8n8.x4.shared.b16 {%0,%1,%2,%3}, [%4];"
        : "=r"(r[0]), "=r"(r[1]), "=r"(r[2]), "=r"(r[3]) : "r"(addr));
}
__device__ __forceinline__ void ldsm4t(uint32_t addr, uint32_t* r) {
    asm volatile("ldmatrix.sync.aligned.m8n8.x4.trans.shared.b16 {%0,%1,%2,%3}, [%4];"
        : "=r"(r[0]), "=r"(r[1]), "=r"(r[2]), "=r"(r[3]) : "r"(addr));
}
__device__ __forceinline__ void mma_f16(float* c, const uint32_t* a, const uint32_t* b) {
    asm volatile(
        "mma.sync.aligned.m16n8k16.row.col.f32.f16.f16.f32 "
        "{%0,%1,%2,%3}, {%4,%5,%6,%7}, {%8,%9}, {%0,%1,%2,%3};"
        : "+f"(c[0]), "+f"(c[1]), "+f"(c[2]), "+f"(c[3])
        : "r"(a[0]), "r"(a[1]), "r"(a[2]), "r"(a[3]), "r"(b[0]), "r"(b[1]));
}
__device__ __forceinline__ uint32_t packh2(float x, float y) {
    __half2 t = __floats2half2_rn(x, y);
    return *reinterpret_cast<uint32_t*>(&t);
}

// ---------------- converts ----------------
// five plain fp32->fp16 jobs in one launch: x_q, x_kv, wq, wk, wv
__global__ void conv_plain5_kernel(
    const float* __restrict__ s0, __half* __restrict__ d0, int n0,
    const float* __restrict__ s1, __half* __restrict__ d1, int n1,
    const float* __restrict__ s2, __half* __restrict__ d2, int n2,
    const float* __restrict__ s3, __half* __restrict__ d3, int n3,
    const float* __restrict__ s4, __half* __restrict__ d4, int n4c)
{
    int i = blockIdx.x * blockDim.x + threadIdx.x;
    const float* s; __half* d;
    if (i < n0)                       { s = s0; d = d0; }
    else if (i < n0+n1)               { s = s1; d = d1; i -= n0; }
    else if (i < n0+n1+n2)            { s = s2; d = d2; i -= n0+n1; }
    else if (i < n0+n1+n2+n3)         { s = s3; d = d3; i -= n0+n1+n2; }
    else if (i < n0+n1+n2+n3+n4c)     { s = s4; d = d4; i -= n0+n1+n2+n3; }
    else return;
    float4 v = ((const float4*)s)[i];
    ((__half2*)d)[2*i]   = __floats2half2_rn(v.x, v.y);
    ((__half2*)d)[2*i+1] = __floats2half2_rn(v.z, v.w);
}

// single split (hi/lo) job: wo
__global__ void conv_split1_kernel(
    const float* __restrict__ s, __half* __restrict__ hh, __half* __restrict__ ll, int n)
{
    int i = blockIdx.x * blockDim.x + threadIdx.x;
    if (i >= n) return;
    float4 v = ((const float4*)s)[i];
    __half a0 = __float2half(v.x), a1 = __float2half(v.y);
    __half a2 = __float2half(v.z), a3 = __float2half(v.w);
    ((__half2*)hh)[2*i]   = __halves2half2(a0, a1);
    ((__half2*)hh)[2*i+1] = __halves2half2(a2, a3);
    ((__half2*)ll)[2*i]   = __floats2half2_rn(v.x - __half2float(a0), v.y - __half2float(a1));
    ((__half2*)ll)[2*i+1] = __floats2half2_rn(v.z - __half2float(a2), v.w - __half2float(a3));
}

// ---------------- RoPE table ----------------
// freq: fp64 exp rounded to fp32 (matches reference); angle reduced in fp64,
// then fp32 sin/cos on [-pi, pi].
__global__ void rope_table_kernel()
{
    int idx = blockIdx.x * blockDim.x + threadIdx.x;
    if (idx >= SQ_ * 32) return;
    int s = idx >> 5;
    int i = idx & 31;
    float freq = (float)exp(-(double)i * log(10000.0) / 32.0);
    float ang  = (float)s * freq;                    // fp32 angle (matches ref)
    double red = remainder((double)ang, 6.283185307179586476925286766559);
    float rf = (float)red;
    g_cos[idx] = cosf(rf);
    g_sin[idx] = sinf(rf);
}

// =============== single-pass fp16 GEMM: Ch = (A @ W^T + bias) [rope/scale] ===============
// BM=BN=128, BK=64, 256 threads (8 warps 4x2), warp tile 32x64. 2 CTAs/SM.
#define GPS 18432   // plane bytes: 128 rows * 144
__global__ __launch_bounds__(256, 2) void gemm_h_kernel(
    const __half* __restrict__ Ah, const __half* __restrict__ Wh,
    const float* __restrict__ bias, __half* __restrict__ Ch,
    int rope, float scale)
{
    const int K = D_, N = D_;
    extern __shared__ char smem[];
    const uint32_t sb = smem_u32(smem);
    const int tid  = threadIdx.x;
    const int lane = tid & 31, wid = tid >> 5;
    const int wm = wid >> 1, wn = wid & 1;
    const int rowBase = blockIdx.y * 128, colBase = blockIdx.x * 128;

    float acc[2][8][4];
#pragma unroll
    for (int i = 0; i < 2; ++i)
#pragma unroll
        for (int j = 0; j < 8; ++j)
#pragma unroll
            for (int q = 0; q < 4; ++q) acc[i][j][q] = 0.f;

#define GH_PREFETCH(kc, bf)                                                    \
    {                                                                          \
        _Pragma("unroll")                                                      \
        for (int i = 0; i < 4; ++i) {                                          \
            int id = tid + i * 256;                                            \
            int r = id >> 3, c = id & 7;                                       \
            cp16(sb + ((bf)*2 + 0) * GPS + r * 144 + c * 16,                   \
                 Ah + (size_t)(rowBase + r) * K + (kc) + c * 8);               \
            cp16(sb + ((bf)*2 + 1) * GPS + r * 144 + c * 16,                   \
                 Wh + (size_t)(colBase + r) * K + (kc) + c * 8);               \
        }                                                                      \
    }

    GH_PREFETCH(0, 0);
    CP_COMMIT();

    int buf = 0;
    for (int kc = 0; kc < K; kc += 64) {
        if (kc + 64 < K) {
            GH_PREFETCH(kc + 64, buf ^ 1);
            CP_COMMIT();
            CP_WAIT(1);
        } else {
            CP_WAIT(0);
        }
        __syncthreads();

        uint32_t base = sb + buf * 2 * GPS;
        uint32_t aA = base + (wm * 32 + (lane & 15)) * 144 + (lane >> 4) * 16;
        uint32_t aW = base + GPS
                    + (wn * 64 + ((lane >> 4) * 8 + (lane & 7))) * 144
                    + ((lane >> 3) & 1) * 16;
#pragma unroll
        for (int kst = 0; kst < 4; ++kst) {
            uint32_t a0[4], a1[4];
            ldsm4(aA + kst * 32, a0);
            ldsm4(aA + kst * 32 + 16 * 144, a1);
            uint32_t bh[8][2];
#pragma unroll
            for (int p2 = 0; p2 < 4; ++p2) {
                uint32_t r[4];
                ldsm4(aW + p2 * 16 * 144 + kst * 32, r);
                bh[2*p2][0] = r[0]; bh[2*p2][1] = r[1];
                bh[2*p2+1][0] = r[2]; bh[2*p2+1][1] = r[3];
            }
#pragma unroll
            for (int j = 0; j < 8; ++j) {
                mma_f16(acc[0][j], a0, bh[j]);
                mma_f16(acc[1][j], a1, bh[j]);
            }
        }
        __syncthreads();
        buf ^= 1;
    }

#pragma unroll
    for (int i = 0; i < 2; ++i) {
        int r0 = rowBase + wm * 32 + i * 16 + (lane >> 2);
        int r1 = r0 + 8;
#pragma unroll
        for (int j = 0; j < 8; ++j) {
            int c0 = colBase + wn * 64 + j * 8 + (lane & 3) * 2;
            float v00 = acc[i][j][0] + bias[c0];
            float v01 = acc[i][j][1] + bias[c0 + 1];
            float v10 = acc[i][j][2] + bias[c0];
            float v11 = acc[i][j][3] + bias[c0 + 1];
            if (rope) {
                int ii = (c0 & 63) >> 1;
                int s0 = r0 & (SQ_ - 1), s1 = r1 & (SQ_ - 1);
                float cs = g_cos[s0 * 32 + ii], sn = g_sin[s0 * 32 + ii];
                float e = v00, o = v01;
                v00 = e * cs - o * sn; v01 = e * sn + o * cs;
                cs = g_cos[s1 * 32 + ii]; sn = g_sin[s1 * 32 + ii];
                e = v10; o = v11;
                v10 = e * cs - o * sn; v11 = e * sn + o * cs;
            }
            v00 *= scale; v01 *= scale; v10 *= scale; v11 *= scale;
            *(__half2*)&Ch[(size_t)r0 * N + c0] = __floats2half2_rn(v00, v01);
            *(__half2*)&Ch[(size_t)r1 * N + c0] = __floats2half2_rn(v10, v11);
        }
    }
}

// =============== split GEMM (3-pass hi/lo): Cf = A @ W^T + bias ===============
__global__ __launch_bounds__(256, 1) void gemm_split_kernel(
    const __half* __restrict__ Ah, const __half* __restrict__ Al,
    const __half* __restrict__ Wh, const __half* __restrict__ Wl,
    const float* __restrict__ bias, float* __restrict__ Cf)
{
    const int K = D_, N = D_;
    extern __shared__ char smem[];
    const uint32_t sb = smem_u32(smem);
    const int tid  = threadIdx.x;
    const int lane = tid & 31, wid = tid >> 5;
    const int wm = wid >> 1, wn = wid & 1;
    const int rowBase = blockIdx.y * 128, colBase = blockIdx.x * 128;

    float acc[2][8][4];
#pragma unroll
    for (int i = 0; i < 2; ++i)
#pragma unroll
        for (int j = 0; j < 8; ++j)
#pragma unroll
            for (int q = 0; q < 4; ++q) acc[i][j][q] = 0.f;

    const __half* gsrc[4] = {Ah, Al, Wh, Wl};

#define GEMM_PREFETCH(kc, bf)                                                  \
    {                                                                          \
        _Pragma("unroll")                                                      \
        for (int p = 0; p < 4; ++p) {                                          \
            const __half* g = gsrc[p];                                         \
            int rb = (p < 2) ? rowBase : colBase;                              \
            _Pragma("unroll")                                                  \
            for (int i = 0; i < 4; ++i) {                                      \
                int id = tid + i * 256;                                        \
                int r = id >> 3, c = id & 7;                                   \
                cp16(sb + ((bf)*4 + p) * GPS + r * 144 + c * 16,               \
                     g + (size_t)(rb + r) * K + (kc) + c * 8);                 \
            }                                                                  \
        }                                                                      \
    }

    GEMM_PREFETCH(0, 0);
    CP_COMMIT();

    int buf = 0;
    for (int kc = 0; kc < K; kc += 64) {
        if (kc + 64 < K) {
            GEMM_PREFETCH(kc + 64, buf ^ 1);
            CP_COMMIT();
            CP_WAIT(1);
        } else {
            CP_WAIT(0);
        }
        __syncthreads();

        uint32_t base = sb + buf * 4 * GPS;
        uint32_t aA = base + (wm * 32 + (lane & 15)) * 144 + (lane >> 4) * 16;
        uint32_t aW = base + 2 * GPS
                    + (wn * 64 + ((lane >> 4) * 8 + (lane & 7))) * 144
                    + ((lane >> 3) & 1) * 16;
#pragma unroll
        for (int kst = 0; kst < 4; ++kst) {
            uint32_t ah0[4], ah1[4], al0[4], al1[4];
            ldsm4(aA + kst * 32, ah0);
            ldsm4(aA + kst * 32 + 16 * 144, ah1);
            ldsm4(aA + GPS + kst * 32, al0);
            ldsm4(aA + GPS + kst * 32 + 16 * 144, al1);
            uint32_t bh[8][2], bl[8][2];
#pragma unroll
            for (int p2 = 0; p2 < 4; ++p2) {
                uint32_t r[4];
                ldsm4(aW + p2 * 16 * 144 + kst * 32, r);
                bh[2*p2][0] = r[0]; bh[2*p2][1] = r[1];
                bh[2*p2+1][0] = r[2]; bh[2*p2+1][1] = r[3];
                ldsm4(aW + GPS + p2 * 16 * 144 + kst * 32, r);
                bl[2*p2][0] = r[0]; bl[2*p2][1] = r[1];
                bl[2*p2+1][0] = r[2]; bl[2*p2+1][1] = r[3];
            }
#pragma unroll
            for (int j = 0; j < 8; ++j) {
                mma_f16(acc[0][j], ah0, bh[j]);
                mma_f16(acc[0][j], ah0, bl[j]);
                mma_f16(acc[0][j], al0, bh[j]);
                mma_f16(acc[1][j], ah1, bh[j]);
                mma_f16(acc[1][j], ah1, bl[j]);
                mma_f16(acc[1][j], al1, bh[j]);
            }
        }
        __syncthreads();
        buf ^= 1;
    }

#pragma unroll
    for (int i = 0; i < 2; ++i) {
        int r0 = rowBase + wm * 32 + i * 16 + (lane >> 2);
        int r1 = r0 + 8;
#pragma unroll
        for (int j = 0; j < 8; ++j) {
            int c0 = colBase + wn * 64 + j * 8 + (lane & 3) * 2;
            Cf[(size_t)r0 * N + c0]     = acc[i][j][0] + bias[c0];
            Cf[(size_t)r0 * N + c0 + 1] = acc[i][j][1] + bias[c0 + 1];
            Cf[(size_t)r1 * N + c0]     = acc[i][j][2] + bias[c0];
            Cf[(size_t)r1 * N + c0 + 1] = acc[i][j][3] + bias[c0 + 1];
        }
    }
}

// =============== Flash attention (mma.sync fp16, online softmax) ===============
#define FPS 9216    // 64 rows * 144B
__global__ __launch_bounds__(128, 2) void flash16_kernel()
{
    extern __shared__ char smem[];
    const uint32_t sb = smem_u32(smem);
    const int tid = threadIdx.x, lane = tid & 31, wid = tid >> 5;
    const int qt = blockIdx.x, bh = blockIdx.y;
    const int b = bh >> 4, h = bh & 15;

    const uint32_t sQ = sb;

#pragma unroll
    for (int i = 0; i < 4; ++i) {
        int id = tid + i * 128;
        int r = id >> 3, c = id & 7;
        cp16(sQ + r * 144 + c * 16,
             g_Qh + (((size_t)(b * SQ_ + qt * 64 + r)) * H_ + h) * 64 + c * 8);
    }
    CP_COMMIT();

#define KV_PREFETCH(t0, bf)                                                    \
    {                                                                          \
        _Pragma("unroll")                                                      \
        for (int i = 0; i < 4; ++i) {                                          \
            int id = tid + i * 128;                                            \
            int r = id >> 3, c = id & 7;                                       \
            size_t go = (((size_t)(b * SQ_ + (t0) + r)) * H_ + h) * 64 + c * 8;\
            cp16(sb + FPS + ((bf)*2 + 0) * FPS + r * 144 + c * 16, g_Kh + go); \
            cp16(sb + FPS + ((bf)*2 + 1) * FPS + r * 144 + c * 16, g_Vh + go); \
        }                                                                      \
    }

    KV_PREFETCH(0, 0);
    CP_COMMIT();

    float oacc[8][4];
#pragma unroll
    for (int j = 0; j < 8; ++j)
#pragma unroll
        for (int q = 0; q < 4; ++q) oacc[j][q] = 0.f;
    float m0 = -1e30f, m1 = -1e30f, l0 = 0.f, l1 = 0.f;
    uint32_t qf[4][4];

    int buf = 0;
    for (int t0 = 0; t0 < SQ_; t0 += 64) {
        if (t0 + 64 < SQ_) {
            KV_PREFETCH(t0 + 64, buf ^ 1);
            CP_COMMIT();
            CP_WAIT(1);
        } else {
            CP_WAIT(0);
        }
        __syncthreads();

        if (t0 == 0) {
            uint32_t aQ = sQ + (wid * 16 + (lane & 15)) * 144 + (lane >> 4) * 16;
#pragma unroll
            for (int kst = 0; kst < 4; ++kst) ldsm4(aQ + kst * 32, qf[kst]);
        }

        uint32_t sK = sb + FPS + (buf * 2) * FPS;
        uint32_t sV = sK + FPS;

        float s[8][4];
#pragma unroll
        for (int j = 0; j < 8; ++j)
#pragma unroll
            for (int q = 0; q < 4; ++q) s[j][q] = 0.f;
        uint32_t aK = sK + ((lane >> 4) * 8 + (lane & 7)) * 144 + ((lane >> 3) & 1) * 16;
#pragma unroll
        for (int kst = 0; kst < 4; ++kst) {
#pragma unroll
            for (int p2 = 0; p2 < 4; ++p2) {
                uint32_t r[4];
                ldsm4(aK + p2 * 16 * 144 + kst * 32, r);
                mma_f16(s[2*p2],     qf[kst], &r[0]);
                mma_f16(s[2*p2 + 1], qf[kst], &r[2]);
            }
        }

        float mt0 = -1e30f, mt1 = -1e30f;
#pragma unroll
        for (int j = 0; j < 8; ++j) {
            mt0 = fmaxf(mt0, fmaxf(s[j][0], s[j][1]));
            mt1 = fmaxf(mt1, fmaxf(s[j][2], s[j][3]));
        }
        mt0 = fmaxf(mt0, __shfl_xor_sync(0xffffffffu, mt0, 1));
        mt0 = fmaxf(mt0, __shfl_xor_sync(0xffffffffu, mt0, 2));
        mt1 = fmaxf(mt1, __shfl_xor_sync(0xffffffffu, mt1, 1));
        mt1 = fmaxf(mt1, __shfl_xor_sync(0xffffffffu, mt1, 2));
        float mn0 = fmaxf(m0, mt0), mn1 = fmaxf(m1, mt1);
        float cr0 = __expf(m0 - mn0), cr1 = __expf(m1 - mn1);
        m0 = mn0; m1 = mn1;
        float ps0 = 0.f, ps1 = 0.f;
#pragma unroll
        for (int j = 0; j < 8; ++j) {
            s[j][0] = __expf(s[j][0] - mn0);
            s[j][1] = __expf(s[j][1] - mn0);
            s[j][2] = __expf(s[j][2] - mn1);
            s[j][3] = __expf(s[j][3] - mn1);
            ps0 += s[j][0] + s[j][1];
            ps1 += s[j][2] + s[j][3];
        }
        ps0 += __shfl_xor_sync(0xffffffffu, ps0, 1);
        ps0 += __shfl_xor_sync(0xffffffffu, ps0, 2);
        ps1 += __shfl_xor_sync(0xffffffffu, ps1, 1);
        ps1 += __shfl_xor_sync(0xffffffffu, ps1, 2);
        l0 = l0 * cr0 + ps0;
        l1 = l1 * cr1 + ps1;
#pragma unroll
        for (int j = 0; j < 8; ++j) {
            oacc[j][0] *= cr0; oacc[j][1] *= cr0;
            oacc[j][2] *= cr1; oacc[j][3] *= cr1;
        }

        uint32_t pf[4][4];
#pragma unroll
        for (int kt = 0; kt < 4; ++kt) {
            pf[kt][0] = packh2(s[2*kt][0],   s[2*kt][1]);
            pf[kt][1] = packh2(s[2*kt][2],   s[2*kt][3]);
            pf[kt][2] = packh2(s[2*kt+1][0], s[2*kt+1][1]);
            pf[kt][3] = packh2(s[2*kt+1][2], s[2*kt+1][3]);
        }

#pragma unroll
        for (int kt = 0; kt < 4; ++kt) {
            uint32_t aV = sV + (kt * 16 + (lane & 7) + ((lane >> 3) & 1) * 8) * 144
                        + (lane >> 4) * 16;
#pragma unroll
            for (int p2 = 0; p2 < 4; ++p2) {
                uint32_t r[4];
                ldsm4t(aV + p2 * 32, r);
                mma_f16(oacc[2*p2],     pf[kt], &r[0]);
                mma_f16(oacc[2*p2 + 1], pf[kt], &r[2]);
            }
        }
        __syncthreads();
        buf ^= 1;
    }

    float inv0 = 1.f / l0, inv1 = 1.f / l1;
    int r0 = qt * 64 + wid * 16 + (lane >> 2);
    size_t base0 = (((size_t)(b * SQ_ + r0)) * H_ + h) * 64;
    size_t base1 = base0 + (size_t)8 * H_ * 64;
#pragma unroll
    for (int j = 0; j < 8; ++j) {
        int c = j * 8 + (lane & 3) * 2;
        float v00 = oacc[j][0] * inv0, v01 = oacc[j][1] * inv0;
        float v10 = oacc[j][2] * inv1, v11 = oacc[j][3] * inv1;
        __half h00 = __float2half(v00), h01 = __float2half(v01);
        __half h10 = __float2half(v10), h11 = __float2half(v11);
        *(__half2*)&g_ch[base0 + c] = __halves2half2(h00, h01);
        *(__half2*)&g_ch[base1 + c] = __halves2half2(h10, h11);
        *(__half2*)&g_cl[base0 + c] = __halves2half2(
            __float2half(v00 - __half2float(h00)), __float2half(v01 - __half2float(h01)));
        *(__half2*)&g_cl[base1 + c] = __halves2half2(
            __float2half(v10 - __half2float(h10)), __float2half(v11 - __half2float(h11)));
    }
}

// ---------------- launch ----------------
extern "C" void kernel_launch(void* const* d_in, const int* in_sizes, int n_in,
                              void* d_out, int out_size)
{
    (void)in_sizes; (void)n_in; (void)out_size;
    const float* x_q  = (const float*)d_in[0];
    const float* x_kv = (const float*)d_in[1];
    const float* wq   = (const float*)d_in[2];
    const float* bq   = (const float*)d_in[3];
    const float* wk   = (const float*)d_in[4];
    const float* bk   = (const float*)d_in[5];
    const float* wv   = (const float*)d_in[6];
    const float* bv   = (const float*)d_in[7];
    const float* wo   = (const float*)d_in[8];
    const float* bo   = (const float*)d_in[9];
    float* out = (float*)d_out;

    __half *xqh, *xkh, *wqh, *wkh, *wvh, *woh, *wol;
    __half *Qh, *Kh, *Vh, *ch, *cl;
    cudaGetSymbolAddress((void**)&xqh, g_xqh);
    cudaGetSymbolAddress((void**)&xkh, g_xkh);
    cudaGetSymbolAddress((void**)&wqh, g_wqh);
    cudaGetSymbolAddress((void**)&wkh, g_wkh);
    cudaGetSymbolAddress((void**)&wvh, g_wvh);
    cudaGetSymbolAddress((void**)&woh, g_woh); cudaGetSymbolAddress((void**)&wol, g_wol);
    cudaGetSymbolAddress((void**)&Qh,  g_Qh);  cudaGetSymbolAddress((void**)&Kh,  g_Kh);
    cudaGetSymbolAddress((void**)&Vh,  g_Vh);
    cudaGetSymbolAddress((void**)&ch,  g_ch);  cudaGetSymbolAddress((void**)&cl,  g_cl);

    const int M  = B_ * SQ_;               // 4096
    const int NX = M * D_ / 4;             // 1,048,576 float4
    const int NW = D_ * D_ / 4;            // 262,144 float4

    conv_plain5_kernel<<<(2*NX + 3*NW + 255) / 256, 256>>>(
        x_q, xqh, NX, x_kv, xkh, NX, wq, wqh, NW, wk, wkh, NW, wv, wvh, NW);
    conv_split1_kernel<<<(NW + 255) / 256, 256>>>(wo, woh, wol, NW);
    rope_table_kernel<<<(SQ_ * 32 + 255) / 256, 256>>>();

    dim3 gemmGrid(D_ / 128, M / 128);      // (8, 32)
    const int ghSmem = 2 * 2 * GPS;        // 73728
    const int gsSmem = 2 * 4 * GPS;        // 147456
    cudaFuncSetAttribute(gemm_h_kernel,
                         cudaFuncAttributeMaxDynamicSharedMemorySize, ghSmem);
    cudaFuncSetAttribute(gemm_split_kernel,
                         cudaFuncAttributeMaxDynamicSharedMemorySize, gsSmem);

    gemm_h_kernel<<<gemmGrid, 256, ghSmem>>>(xqh, wqh, bq, Qh, 1, 0.125f);
    gemm_h_kernel<<<gemmGrid, 256, ghSmem>>>(xkh, wkh, bk, Kh, 1, 1.0f);
    gemm_h_kernel<<<gemmGrid, 256, ghSmem>>>(xkh, wvh, bv, Vh, 0, 1.0f);

    const int flashSmem = 5 * FPS;         // 46080
    cudaFuncSetAttribute(flash16_kernel,
                         cudaFuncAttributeMaxDynamicSharedMemorySize, flashSmem);
    flash16_kernel<<<dim3(SQ_ / 64, B_ * H_), 128, flashSmem>>>();

    gemm_split_kernel<<<gemmGrid, 256, gsSmem>>>(ch, cl, woh, wol, bo, out);
}